// round 12
// baseline (speedup 1.0000x reference)
#include <cuda_runtime.h>
#include <cuda_fp16.h>
#include <math_constants.h>
#include <cstdint>

// Problem constants
#define B_  4
#define N_  8192
#define M_  2048
#define C1_ 128
#define C2_ 256
#define K0_ 384   // C1 + C2
#define K1_ 256
#define CO_ 256
#define BN_ (B_ * N_)
#define BM_ (B_ * M_)

// ---------------- scratch (static __device__ globals; no allocations) ----------
__device__ int   g_idx[(size_t)BN_ * 3];
__device__ float g_wgt[(size_t)BN_ * 3];
__device__ __align__(16) __half g_kfh[(size_t)BM_ * C2_];  // kf^T fp16 (B*M, 256)
__device__ __align__(16) __half g_ufh[(size_t)BN_ * C1_];  // uf^T fp16 (B*N, 128)
__device__ __align__(16) float  g_z [(size_t)BM_ * CO_];   // Z = kf^T . W0a^T fp32
__device__ __align__(16) float  g_yb[(size_t)BN_ * CO_];   // uf^T . W0b^T fp32
__device__ __align__(16) __half g_hh[(size_t)BN_ * K1_];   // layer0 out fp16 (B*N, 256)
__device__ __align__(16) __half g_W0a[CO_ * C2_];          // W0[:, 0:256]  fp16 (folded)
__device__ __align__(16) __half g_W0b[CO_ * C1_];          // W0[:, 256:384] fp16 (folded)
__device__ __align__(16) __half g_W1h[CO_ * K1_];
__device__ float g_b0f[CO_], g_b1f[CO_];

// ================= PTX helpers (baseline ISA only) ==============================
__device__ __forceinline__ uint32_t smem_u32(const void* p) {
    uint32_t a;
    asm("{ .reg .u64 t; cvta.to.shared.u64 t, %1; cvt.u32.u64 %0, t; }" : "=r"(a) : "l"(p));
    return a;
}
__device__ __forceinline__ void cpa16(uint32_t dst, const void* src) {
    asm volatile("cp.async.ca.shared.global [%0], [%1], 16;" :: "r"(dst), "l"(src));
}
#define CP_COMMIT()  asm volatile("cp.async.commit_group;" ::: "memory")
#define CP_WAIT2()   asm volatile("cp.async.wait_group 2;" ::: "memory")
#define CP_WAITALL() asm volatile("cp.async.wait_all;" ::: "memory")

__device__ __forceinline__ void ldsm4(uint32_t* r, uint32_t addr) {
    asm volatile("ldmatrix.sync.aligned.m8n8.x4.shared.b16 {%0,%1,%2,%3}, [%4];"
                 : "=r"(r[0]), "=r"(r[1]), "=r"(r[2]), "=r"(r[3]) : "r"(addr));
}
__device__ __forceinline__ void mma16816(float* c, const uint32_t* a, const uint32_t* b) {
    asm volatile("mma.sync.aligned.m16n8k16.row.col.f32.f16.f16.f32 "
                 "{%0,%1,%2,%3},{%4,%5,%6,%7},{%8,%9},{%0,%1,%2,%3};"
                 : "+f"(c[0]), "+f"(c[1]), "+f"(c[2]), "+f"(c[3])
                 : "r"(a[0]), "r"(a[1]), "r"(a[2]), "r"(a[3]), "r"(b[0]), "r"(b[1]));
}
#define SW128(o) ((o) ^ (((o) >> 3) & 0x70))

// ---------------- BN fold (merged: block-range dispatch, index streams identical) -
__global__ void fold_bn_kernel(const float* __restrict__ W0, const float* __restrict__ b0,
                               const float* __restrict__ g0, const float* __restrict__ be0,
                               const float* __restrict__ rm0, const float* __restrict__ rv0,
                               const float* __restrict__ W1, const float* __restrict__ b1,
                               const float* __restrict__ g1, const float* __restrict__ be1,
                               const float* __restrict__ rm1, const float* __restrict__ rv1) {
    if (blockIdx.x < 384) {
        // fold0: i identical to the standalone kernel with 384 blocks
        int i = blockIdx.x * blockDim.x + threadIdx.x;
        if (i < CO_ * K0_) {
            int co = i / K0_, col = i - co * K0_;
            float s = g0[co] / sqrtf(rv0[co] + 1e-5f);
            __half w = __float2half_rn(W0[i] * s);
            if (col < C2_) g_W0a[co * C2_ + col] = w;
            else           g_W0b[co * C1_ + (col - C2_)] = w;
        }
        if (i < CO_) {
            float s = g0[i] / sqrtf(rv0[i] + 1e-5f);
            g_b0f[i] = (b0[i] - rm0[i]) * s + be0[i];
        }
    } else {
        // fold1: i identical to the standalone kernel with 256 blocks
        int i = (blockIdx.x - 384) * blockDim.x + threadIdx.x;
        if (i < CO_ * K1_) {
            int co = i / K1_;
            float s = g1[co] / sqrtf(rv1[co] + 1e-5f);
            g_W1h[i] = __float2half_rn(W1[i] * s);
        }
        if (i < CO_) {
            float s = g1[i] / sqrtf(rv1[i] + 1e-5f);
            g_b1f[i] = (b1[i] - rm1[i]) * s + be1[i];
        }
    }
}

// ---------------- transpose known_feats (B,C2,M) -> (B*M, 256) fp16 -------------
__global__ void transpose_kf_kernel(const float* __restrict__ kf) {
    __shared__ float tile[32][33];
    int b = blockIdx.z, m0 = blockIdx.x * 32, c0 = blockIdx.y * 32;
    int tx = threadIdx.x, ty = threadIdx.y;
#pragma unroll
    for (int j = 0; j < 32; j += 8)
        tile[ty + j][tx] = kf[((size_t)b * C2_ + c0 + ty + j) * M_ + m0 + tx];
    __syncthreads();
#pragma unroll
    for (int j = 0; j < 32; j += 8) {
        float v = tile[tx][ty + j];
        size_t o = ((size_t)b * M_ + m0 + ty + j) * C2_ + c0 + tx;
        g_kfh[o] = __float2half_rn(v);
    }
}

// ---------------- transpose unknow_feats (B,C1,N) -> (B*N, 128) fp16 ------------
__global__ void transpose_uf_kernel(const float* __restrict__ uf) {
    __shared__ float tile[32][33];
    int b = blockIdx.z, n0 = blockIdx.x * 32, c0 = blockIdx.y * 32;
    int tx = threadIdx.x, ty = threadIdx.y;
#pragma unroll
    for (int j = 0; j < 32; j += 8)
        tile[ty + j][tx] = uf[((size_t)b * C1_ + c0 + ty + j) * N_ + n0 + tx];
    __syncthreads();
#pragma unroll
    for (int j = 0; j < 32; j += 8) {
        float v = tile[tx][ty + j];
        size_t o = ((size_t)b * N_ + n0 + ty + j) * C1_ + c0 + tx;
        g_ufh[o] = __float2half_rn(v);
    }
}

// ---------------- three_nn body: warp-per-chunk, lane = point --------------------
#define TNN_UPDATE(dv, mi)                                            \
    do {                                                              \
        if ((dv) < d2) {                                              \
            if ((dv) < d1) {                                          \
                d2 = d1; i2 = i1;                                     \
                if ((dv) < d0) { d1 = d0; i1 = i0; d0 = (dv); i0 = (mi); } \
                else           { d1 = (dv); i1 = (mi); }              \
            } else { d2 = (dv); i2 = (mi); }                          \
        }                                                             \
    } while (0)

#define TNN_LESS(dv, mi, d, i) ((dv) < (d) || ((dv) == (d) && (mi) < (i)))
#define TNN_UPDATE_TB(dv, mi)                                         \
    do {                                                              \
        if (TNN_LESS(dv, mi, d2, i2)) {                               \
            if (TNN_LESS(dv, mi, d1, i1)) {                           \
                d2 = d1; i2 = i1;                                     \
                if (TNN_LESS(dv, mi, d0, i0)) { d1 = d0; i1 = i0; d0 = (dv); i0 = (mi); } \
                else                          { d1 = (dv); i1 = (mi); } \
            } else { d2 = (dv); i2 = (mi); }                          \
        }                                                             \
    } while (0)

// b = batch, nb = 32-point block index
__device__ void three_nn_body(const float* __restrict__ unknown,
                              const float* __restrict__ known, int b, int nb) {
    __shared__ float4 sk[M_];          // 32 KB
    __shared__ float  sd[8][3][32];
    __shared__ int    si[8][3][32];
    const float* kb = known + (size_t)b * M_ * 3;
    for (int m = threadIdx.x; m < M_; m += blockDim.x) {
        float x = kb[m * 3 + 0], y = kb[m * 3 + 1], z = kb[m * 3 + 2];
        sk[m] = make_float4(x, y, z, x * x + y * y + z * z);
    }
    __syncthreads();

    int lane = threadIdx.x & 31;
    int w    = threadIdx.x >> 5;
    int n    = nb * 32 + lane;
    const float* u = unknown + ((size_t)b * N_ + n) * 3;
    float ux = u[0], uy = u[1], uz = u[2];
    float un = ux * ux + uy * uy + uz * uz;
    float ax = -2.f * ux, ay = -2.f * uy, az = -2.f * uz;

    float d0 = CUDART_INF_F, d1 = CUDART_INF_F, d2 = CUDART_INF_F;
    int   i0 = 0, i1 = 0, i2 = 0;
    int mStart = w * (M_ / 8);
    for (int m = mStart; m < mStart + M_ / 8; m += 4) {
        float4 pa = sk[m + 0];
        float4 pb = sk[m + 1];
        float4 pc = sk[m + 2];
        float4 pd = sk[m + 3];
        float da = fmaf(ax, pa.x, fmaf(ay, pa.y, fmaf(az, pa.z, un + pa.w)));
        float db = fmaf(ax, pb.x, fmaf(ay, pb.y, fmaf(az, pb.z, un + pb.w)));
        float dc = fmaf(ax, pc.x, fmaf(ay, pc.y, fmaf(az, pc.z, un + pc.w)));
        float dd = fmaf(ax, pd.x, fmaf(ay, pd.y, fmaf(az, pd.z, un + pd.w)));
        TNN_UPDATE(da, m + 0);
        TNN_UPDATE(db, m + 1);
        TNN_UPDATE(dc, m + 2);
        TNN_UPDATE(dd, m + 3);
    }
    sd[w][0][lane] = d0; si[w][0][lane] = i0;
    sd[w][1][lane] = d1; si[w][1][lane] = i1;
    sd[w][2][lane] = d2; si[w][2][lane] = i2;
    __syncthreads();

    if (w == 0) {
        d0 = d1 = d2 = CUDART_INF_F;
        i0 = i1 = i2 = 0;
#pragma unroll
        for (int ww = 0; ww < 8; ww++) {
#pragma unroll
            for (int k = 0; k < 3; k++) {
                float dv = sd[ww][k][lane];
                int   mi = si[ww][k][lane];
                TNN_UPDATE_TB(dv, mi);
            }
        }
        float s0 = sqrtf(fmaxf(d0, 0.f)), s1 = sqrtf(fmaxf(d1, 0.f)), s2 = sqrtf(fmaxf(d2, 0.f));
        float r0 = 1.f / (s0 + 1e-8f), r1 = 1.f / (s1 + 1e-8f), r2 = 1.f / (s2 + 1e-8f);
        float rs = r0 + r1 + r2;
        size_t base = ((size_t)b * N_ + n) * 3;
        g_idx[base + 0] = i0; g_idx[base + 1] = i1; g_idx[base + 2] = i2;
        g_wgt[base + 0] = r0 / rs; g_wgt[base + 1] = r1 / rs; g_wgt[base + 2] = r2 / rs;
    }
}

// =================================================================================
// Single-fp16 GEMM body via mma.sync.m16n8k16 (identical math to R11).
// MODE 0: Z  = kf_t(8192, K=256) . W0a  -> g_z  fp32
// MODE 1: yb = uf_t(32768, K=128) . W0b -> g_yb fp32
// MODE 2: out = W1(K=256) . h(32768)    -> dout (B,CO,N) fp32, bias+relu
// bx = weight-tile (or co-tile for MODE2), by = point-tile (or point for MODE2)
// =================================================================================
static constexpr int STAGE_BYTES = 16384;
static constexpr int GEMM_SMEM   = 4 * STAGE_BYTES;   // 64 KB

template<int K>
__device__ __forceinline__ void load_stage(
        uint32_t sb, int stage,
        const __half* __restrict__ A, const __half* __restrict__ Bm,
        int m0, int n0, int k0, int tid) {
    uint32_t base = sb + (uint32_t)stage * STAGE_BYTES;
#pragma unroll
    for (int i = 0; i < 4; i++) {
        int e = tid + i * 256;
        int t = e >> 9;
        int l = e & 511;
        int r = l >> 2, q = l & 3;
        uint32_t dsw = SW128((uint32_t)(r * 64 + q * 16));
        const __half* src = (t == 0) ? (A  + (size_t)(m0 + r) * K + k0 + q * 8)
                                     : (Bm + (size_t)(n0 + r) * K + k0 + q * 8);
        cpa16(base + (uint32_t)t * 8192 + dsw, src);
    }
}

template<int MODE>
__device__ void gemm_body(float* __restrict__ dout, int bx, int by) {
    constexpr int  K  = (MODE == 1) ? C1_ : 256;
    constexpr int  CH = K / 32;
    const __half* __restrict__ A  = (MODE == 0) ? g_kfh : (MODE == 1) ? g_ufh : g_W1h;
    const __half* __restrict__ Bm = (MODE == 0) ? g_W0a : (MODE == 1) ? g_W0b : g_hh;

    int m0 = (MODE == 2 ? bx : by) * 128;
    int n0 = (MODE == 2 ? by : bx) * 128;

    extern __shared__ char smem[];
    uint32_t sb = smem_u32(smem);
    int tid = threadIdx.x, wid = tid >> 5, lane = tid & 31;
    int warp_m = (wid & 1) * 64;
    int warp_n = (wid >> 1) * 32;

    float acc[4][4][4] = {};

    load_stage<K>(sb, 0, A, Bm, m0, n0, 0,  tid); CP_COMMIT();
    load_stage<K>(sb, 1, A, Bm, m0, n0, 32, tid); CP_COMMIT();
    load_stage<K>(sb, 2, A, Bm, m0, n0, 64, tid); CP_COMMIT();

    int lrow = lane & 15;
    int lcol = (lane >> 4) * 16;

    for (int c = 0; c < CH; c++) {
        CP_WAIT2();
        __syncthreads();
        if (c + 3 < CH)
            load_stage<K>(sb, (c + 3) & 3, A, Bm, m0, n0, (c + 3) * 32, tid);
        CP_COMMIT();

        uint32_t stg = sb + (uint32_t)(c & 3) * STAGE_BYTES;
#pragma unroll
        for (int kk = 0; kk < 2; kk++) {
            uint32_t a[4][4], b[4][2];
#pragma unroll
            for (int mt = 0; mt < 4; mt++) {
                uint32_t off = (uint32_t)((warp_m + mt * 16 + lrow) * 64 + kk * 32 + lcol);
                ldsm4(a[mt], stg + SW128(off));
            }
#pragma unroll
            for (int np = 0; np < 2; np++) {
                uint32_t off = (uint32_t)((warp_n + np * 16 + lrow) * 64 + kk * 32 + lcol);
                uint32_t r[4];
                ldsm4(r, stg + 8192 + SW128(off));
                b[np * 2][0] = r[0];     b[np * 2][1] = r[2];
                b[np * 2 + 1][0] = r[1]; b[np * 2 + 1][1] = r[3];
            }
#pragma unroll
            for (int mt = 0; mt < 4; mt++)
#pragma unroll
                for (int nt = 0; nt < 4; nt++)
                    mma16816(acc[mt][nt], a[mt], b[nt]);
        }
    }
    CP_WAITALL();

    int gr = lane >> 2;
    int gc = (lane & 3) * 2;

    if (MODE != 2) {
        float* out = (MODE == 0) ? g_z : g_yb;
#pragma unroll
        for (int mt = 0; mt < 4; mt++) {
#pragma unroll
            for (int half = 0; half < 2; half++) {
                int p = m0 + warp_m + mt * 16 + gr + half * 8;
#pragma unroll
                for (int nt = 0; nt < 4; nt++) {
                    int co = n0 + warp_n + nt * 8 + gc;
                    float2 v;
                    v.x = acc[mt][nt][half * 2 + 0];
                    v.y = acc[mt][nt][half * 2 + 1];
                    *(float2*)(out + (size_t)p * CO_ + co) = v;
                }
            }
        }
    } else {
#pragma unroll
        for (int mt = 0; mt < 4; mt++) {
            int co = m0 + warp_m + mt * 16 + gr;
            float bm0 = g_b1f[co], bm8 = g_b1f[co + 8];
#pragma unroll
            for (int nt = 0; nt < 4; nt++) {
                int pt = n0 + warp_n + nt * 8 + gc;
                int bb = pt >> 13;
                int nl = pt & (N_ - 1);
                float2 u0;
                u0.x = fmaxf(acc[mt][nt][0] + bm0, 0.f);
                u0.y = fmaxf(acc[mt][nt][1] + bm0, 0.f);
                *(float2*)(dout + ((size_t)(bb * CO_ + co)) * N_ + nl) = u0;
                float2 u1;
                u1.x = fmaxf(acc[mt][nt][2] + bm8, 0.f);
                u1.y = fmaxf(acc[mt][nt][3] + bm8, 0.f);
                *(float2*)(dout + ((size_t)(bb * CO_ + co + 8)) * N_ + nl) = u1;
            }
        }
    }
}

// ---------------- mega-kernel: z=0 GEMM0, z=1 GEMM1, z=2 three_nn ----------------
// grid (4, 256, 3), block 256, dynamic smem = GEMM_SMEM
__global__ void __launch_bounds__(256, 2)
mega_mid_kernel(float* __restrict__ dout,
                const float* __restrict__ unknown, const float* __restrict__ known) {
    if (blockIdx.z == 0) {
        if (blockIdx.x < 2 && blockIdx.y < (BM_ / 128))
            gemm_body<0>(dout, blockIdx.x, blockIdx.y);
    } else if (blockIdx.z == 1) {
        if (blockIdx.x < 2)
            gemm_body<1>(dout, blockIdx.x, blockIdx.y);
    } else {
        three_nn_body(unknown, known, blockIdx.x, blockIdx.y);
    }
}

// ---------------- layer-1 GEMM (separate launch; depends on combine) -------------
__global__ void __launch_bounds__(256, 2)
gemm2_kernel(float* __restrict__ dout) {
    gemm_body<2>(dout, blockIdx.x, blockIdx.y);
}

// ---------------- combine: h = relu(yb + sum wk * Z[idxk] + b0) fp16 -------------
__global__ void combine_kernel() {
    int lane = threadIdx.x & 31;
    int warp = threadIdx.x >> 5;
    int pid  = blockIdx.x * 8 + warp;
    int b    = pid >> 13;
    size_t base = (size_t)pid * 3;
    int i0 = g_idx[base + 0], i1 = g_idx[base + 1], i2 = g_idx[base + 2];
    float w0 = g_wgt[base + 0], w1 = g_wgt[base + 1], w2 = g_wgt[base + 2];
    const float4* yb = (const float4*)(g_yb + (size_t)pid * CO_);
    const float4* z0 = (const float4*)(g_z + ((size_t)(b * M_ + i0)) * CO_);
    const float4* z1 = (const float4*)(g_z + ((size_t)(b * M_ + i1)) * CO_);
    const float4* z2 = (const float4*)(g_z + ((size_t)(b * M_ + i2)) * CO_);
    const float4* bs = (const float4*)g_b0f;
    __half* hh = g_hh + (size_t)pid * K1_;
#pragma unroll
    for (int it = 0; it < 2; it++) {
        int c = lane + it * 32;
        float4 y = yb[c], a = z0[c], d = z1[c], e = z2[c], bb = bs[c];
        float v[4];
        v[0] = fmaxf(y.x + w0 * a.x + w1 * d.x + w2 * e.x + bb.x, 0.f);
        v[1] = fmaxf(y.y + w0 * a.y + w1 * d.y + w2 * e.y + bb.y, 0.f);
        v[2] = fmaxf(y.z + w0 * a.z + w1 * d.z + w2 * e.z + bb.z, 0.f);
        v[3] = fmaxf(y.w + w0 * a.w + w1 * d.w + w2 * e.w + bb.w, 0.f);
        __half2 h01 = __half2(__float2half_rn(v[0]), __float2half_rn(v[1]));
        __half2 h23 = __half2(__float2half_rn(v[2]), __float2half_rn(v[3]));
        *(__half2*)(hh + c * 4)     = h01;
        *(__half2*)(hh + c * 4 + 2) = h23;
    }
}

// ---------------- launch (single stream, strictly sequential) ---------------------
extern "C" void kernel_launch(void* const* d_in, const int* in_sizes, int n_in,
                              void* d_out, int out_size) {
    (void)in_sizes; (void)n_in; (void)out_size;
    const float* unknown = (const float*)d_in[0];
    const float* known   = (const float*)d_in[1];
    const float* uf      = (const float*)d_in[2];
    const float* kf      = (const float*)d_in[3];
    const float* W0  = (const float*)d_in[4];
    const float* b0  = (const float*)d_in[5];
    const float* g0  = (const float*)d_in[6];
    const float* be0 = (const float*)d_in[7];
    const float* rm0 = (const float*)d_in[8];
    const float* rv0 = (const float*)d_in[9];
    const float* W1  = (const float*)d_in[10];
    const float* b1  = (const float*)d_in[11];
    const float* g1  = (const float*)d_in[12];
    const float* be1 = (const float*)d_in[13];
    const float* rm1 = (const float*)d_in[14];
    const float* rv1 = (const float*)d_in[15];
    float* out = (float*)d_out;

    cudaFuncSetAttribute(mega_mid_kernel, cudaFuncAttributeMaxDynamicSharedMemorySize, GEMM_SMEM);
    cudaFuncSetAttribute(gemm2_kernel,    cudaFuncAttributeMaxDynamicSharedMemorySize, GEMM_SMEM);

    fold_bn_kernel<<<640, 256>>>(W0, b0, g0, be0, rm0, rv0,
                                 W1, b1, g1, be1, rm1, rv1);

    transpose_kf_kernel<<<dim3(M_ / 32, C2_ / 32, B_), dim3(32, 8)>>>(kf);
    transpose_uf_kernel<<<dim3(N_ / 32, C1_ / 32, B_), dim3(32, 8)>>>(uf);

    // GEMM0 (Z) + GEMM1 (YB) + three_nn in one launch
    mega_mid_kernel<<<dim3(4, BN_ / 128, 3), 256, GEMM_SMEM>>>(out, unknown, known);

    combine_kernel<<<BN_ / 8, 256>>>();                                // h fp16
    gemm2_kernel<<<dim3(2, BN_ / 128), 256, GEMM_SMEM>>>(out);         // layer1
}

// round 13
// speedup vs baseline: 1.1646x; 1.1646x over previous
#include <cuda_runtime.h>
#include <cuda_fp16.h>
#include <math_constants.h>
#include <cstdint>

// Problem constants
#define B_  4
#define N_  8192
#define M_  2048
#define C1_ 128
#define C2_ 256
#define K0_ 384   // C1 + C2
#define K1_ 256
#define CO_ 256
#define BN_ (B_ * N_)
#define BM_ (B_ * M_)

// ---------------- scratch (static __device__ globals; no allocations) ----------
__device__ int   g_idx[(size_t)BN_ * 3];
__device__ float g_wgt[(size_t)BN_ * 3];
__device__ __align__(16) __half g_kfh[(size_t)BM_ * C2_];  // kf^T fp16 (B*M, 256)
__device__ __align__(16) __half g_ufh[(size_t)BN_ * C1_];  // uf^T fp16 (B*N, 128)
__device__ __align__(16) float  g_z [(size_t)BM_ * CO_];   // Z = kf^T . W0a^T fp32
__device__ __align__(16) float  g_yb[(size_t)BN_ * CO_];   // uf^T . W0b^T fp32
__device__ __align__(16) __half g_hh[(size_t)BN_ * K1_];   // layer0 out fp16 (B*N, 256)
__device__ __align__(16) __half g_W0a[CO_ * C2_];          // W0[:, 0:256]  fp16 (folded)
__device__ __align__(16) __half g_W0b[CO_ * C1_];          // W0[:, 256:384] fp16 (folded)
__device__ __align__(16) __half g_W1h[CO_ * K1_];
__device__ float g_b0f[CO_], g_b1f[CO_];

// ================= PTX helpers (baseline ISA only) ==============================
__device__ __forceinline__ uint32_t smem_u32(const void* p) {
    uint32_t a;
    asm("{ .reg .u64 t; cvta.to.shared.u64 t, %1; cvt.u32.u64 %0, t; }" : "=r"(a) : "l"(p));
    return a;
}
__device__ __forceinline__ void cpa16(uint32_t dst, const void* src) {
    asm volatile("cp.async.ca.shared.global [%0], [%1], 16;" :: "r"(dst), "l"(src));
}
#define CP_COMMIT()  asm volatile("cp.async.commit_group;" ::: "memory")
#define CP_WAIT2()   asm volatile("cp.async.wait_group 2;" ::: "memory")
#define CP_WAITALL() asm volatile("cp.async.wait_all;" ::: "memory")

__device__ __forceinline__ void ldsm4(uint32_t* r, uint32_t addr) {
    asm volatile("ldmatrix.sync.aligned.m8n8.x4.shared.b16 {%0,%1,%2,%3}, [%4];"
                 : "=r"(r[0]), "=r"(r[1]), "=r"(r[2]), "=r"(r[3]) : "r"(addr));
}
__device__ __forceinline__ void mma16816(float* c, const uint32_t* a, const uint32_t* b) {
    asm volatile("mma.sync.aligned.m16n8k16.row.col.f32.f16.f16.f32 "
                 "{%0,%1,%2,%3},{%4,%5,%6,%7},{%8,%9},{%0,%1,%2,%3};"
                 : "+f"(c[0]), "+f"(c[1]), "+f"(c[2]), "+f"(c[3])
                 : "r"(a[0]), "r"(a[1]), "r"(a[2]), "r"(a[3]), "r"(b[0]), "r"(b[1]));
}
#define SW128(o) ((o) ^ (((o) >> 3) & 0x70))

// ---------------- BN fold (merged: block-range dispatch; proven in R12) ----------
__global__ void fold_bn_kernel(const float* __restrict__ W0, const float* __restrict__ b0,
                               const float* __restrict__ g0, const float* __restrict__ be0,
                               const float* __restrict__ rm0, const float* __restrict__ rv0,
                               const float* __restrict__ W1, const float* __restrict__ b1,
                               const float* __restrict__ g1, const float* __restrict__ be1,
                               const float* __restrict__ rm1, const float* __restrict__ rv1) {
    if (blockIdx.x < 384) {
        int i = blockIdx.x * blockDim.x + threadIdx.x;
        if (i < CO_ * K0_) {
            int co = i / K0_, col = i - co * K0_;
            float s = g0[co] / sqrtf(rv0[co] + 1e-5f);
            __half w = __float2half_rn(W0[i] * s);
            if (col < C2_) g_W0a[co * C2_ + col] = w;
            else           g_W0b[co * C1_ + (col - C2_)] = w;
        }
        if (i < CO_) {
            float s = g0[i] / sqrtf(rv0[i] + 1e-5f);
            g_b0f[i] = (b0[i] - rm0[i]) * s + be0[i];
        }
    } else {
        int i = (blockIdx.x - 384) * blockDim.x + threadIdx.x;
        if (i < CO_ * K1_) {
            int co = i / K1_;
            float s = g1[co] / sqrtf(rv1[co] + 1e-5f);
            g_W1h[i] = __float2half_rn(W1[i] * s);
        }
        if (i < CO_) {
            float s = g1[i] / sqrtf(rv1[i] + 1e-5f);
            g_b1f[i] = (b1[i] - rm1[i]) * s + be1[i];
        }
    }
}

// ---------------- merged transpose: kf blocks then uf blocks ---------------------
// kf: (B,C2,M) -> g_kfh (B*M, 256); grid slice of 2048 blocks (64 x 8 x 4)
// uf: (B,C1,N) -> g_ufh (B*N, 128); grid slice of 4096 blocks (256 x 4 x 4)
__global__ void transpose_all_kernel(const float* __restrict__ kf,
                                     const float* __restrict__ uf) {
    __shared__ float tile[32][33];
    int tx = threadIdx.x, ty = threadIdx.y;
    int blk = blockIdx.x;
    if (blk < 2048) {
        // kf branch: x = m-tile (64), y = c-tile (8), z = b (4)
        int bx = blk & 63, rem = blk >> 6;
        int by = rem & 7,  b = rem >> 3;
        int m0 = bx * 32, c0 = by * 32;
#pragma unroll
        for (int j = 0; j < 32; j += 8)
            tile[ty + j][tx] = kf[((size_t)b * C2_ + c0 + ty + j) * M_ + m0 + tx];
        __syncthreads();
#pragma unroll
        for (int j = 0; j < 32; j += 8) {
            float v = tile[tx][ty + j];
            size_t o = ((size_t)b * M_ + m0 + ty + j) * C2_ + c0 + tx;
            g_kfh[o] = __float2half_rn(v);
        }
    } else {
        // uf branch: x = n-tile (256), y = c-tile (4), z = b (4)
        int e = blk - 2048;
        int bx = e & 255, rem = e >> 8;
        int by = rem & 3,  b = rem >> 2;
        int n0 = bx * 32, c0 = by * 32;
#pragma unroll
        for (int j = 0; j < 32; j += 8)
            tile[ty + j][tx] = uf[((size_t)b * C1_ + c0 + ty + j) * N_ + n0 + tx];
        __syncthreads();
#pragma unroll
        for (int j = 0; j < 32; j += 8) {
            float v = tile[tx][ty + j];
            size_t o = ((size_t)b * N_ + n0 + ty + j) * C1_ + c0 + tx;
            g_ufh[o] = __float2half_rn(v);
        }
    }
}

// ---------------- three_nn: warp-per-chunk, lane = point (R11 champion) ----------
#define TNN_UPDATE(dv, mi)                                            \
    do {                                                              \
        if ((dv) < d2) {                                              \
            if ((dv) < d1) {                                          \
                d2 = d1; i2 = i1;                                     \
                if ((dv) < d0) { d1 = d0; i1 = i0; d0 = (dv); i0 = (mi); } \
                else           { d1 = (dv); i1 = (mi); }              \
            } else { d2 = (dv); i2 = (mi); }                          \
        }                                                             \
    } while (0)

#define TNN_LESS(dv, mi, d, i) ((dv) < (d) || ((dv) == (d) && (mi) < (i)))
#define TNN_UPDATE_TB(dv, mi)                                         \
    do {                                                              \
        if (TNN_LESS(dv, mi, d2, i2)) {                               \
            if (TNN_LESS(dv, mi, d1, i1)) {                           \
                d2 = d1; i2 = i1;                                     \
                if (TNN_LESS(dv, mi, d0, i0)) { d1 = d0; i1 = i0; d0 = (dv); i0 = (mi); } \
                else                          { d1 = (dv); i1 = (mi); } \
            } else { d2 = (dv); i2 = (mi); }                          \
        }                                                             \
    } while (0)

__global__ void three_nn_kernel(const float* __restrict__ unknown,
                                const float* __restrict__ known) {
    __shared__ float4 sk[M_];          // 32 KB
    __shared__ float  sd[8][3][32];
    __shared__ int    si[8][3][32];
    int b = blockIdx.y;
    const float* kb = known + (size_t)b * M_ * 3;
    for (int m = threadIdx.x; m < M_; m += blockDim.x) {
        float x = kb[m * 3 + 0], y = kb[m * 3 + 1], z = kb[m * 3 + 2];
        sk[m] = make_float4(x, y, z, x * x + y * y + z * z);
    }
    __syncthreads();

    int lane = threadIdx.x & 31;
    int w    = threadIdx.x >> 5;
    int n    = blockIdx.x * 32 + lane;
    const float* u = unknown + ((size_t)b * N_ + n) * 3;
    float ux = u[0], uy = u[1], uz = u[2];
    float un = ux * ux + uy * uy + uz * uz;
    float ax = -2.f * ux, ay = -2.f * uy, az = -2.f * uz;

    float d0 = CUDART_INF_F, d1 = CUDART_INF_F, d2 = CUDART_INF_F;
    int   i0 = 0, i1 = 0, i2 = 0;
    int mStart = w * (M_ / 8);
    for (int m = mStart; m < mStart + M_ / 8; m += 4) {
        float4 pa = sk[m + 0];
        float4 pb = sk[m + 1];
        float4 pc = sk[m + 2];
        float4 pd = sk[m + 3];
        float da = fmaf(ax, pa.x, fmaf(ay, pa.y, fmaf(az, pa.z, un + pa.w)));
        float db = fmaf(ax, pb.x, fmaf(ay, pb.y, fmaf(az, pb.z, un + pb.w)));
        float dc = fmaf(ax, pc.x, fmaf(ay, pc.y, fmaf(az, pc.z, un + pc.w)));
        float dd = fmaf(ax, pd.x, fmaf(ay, pd.y, fmaf(az, pd.z, un + pd.w)));
        TNN_UPDATE(da, m + 0);
        TNN_UPDATE(db, m + 1);
        TNN_UPDATE(dc, m + 2);
        TNN_UPDATE(dd, m + 3);
    }
    sd[w][0][lane] = d0; si[w][0][lane] = i0;
    sd[w][1][lane] = d1; si[w][1][lane] = i1;
    sd[w][2][lane] = d2; si[w][2][lane] = i2;
    __syncthreads();

    if (w == 0) {
        d0 = d1 = d2 = CUDART_INF_F;
        i0 = i1 = i2 = 0;
#pragma unroll
        for (int ww = 0; ww < 8; ww++) {
#pragma unroll
            for (int k = 0; k < 3; k++) {
                float dv = sd[ww][k][lane];
                int   mi = si[ww][k][lane];
                TNN_UPDATE_TB(dv, mi);
            }
        }
        float s0 = sqrtf(fmaxf(d0, 0.f)), s1 = sqrtf(fmaxf(d1, 0.f)), s2 = sqrtf(fmaxf(d2, 0.f));
        float r0 = 1.f / (s0 + 1e-8f), r1 = 1.f / (s1 + 1e-8f), r2 = 1.f / (s2 + 1e-8f);
        float rs = r0 + r1 + r2;
        size_t base = ((size_t)b * N_ + n) * 3;
        g_idx[base + 0] = i0; g_idx[base + 1] = i1; g_idx[base + 2] = i2;
        g_wgt[base + 0] = r0 / rs; g_wgt[base + 1] = r1 / rs; g_wgt[base + 2] = r2 / rs;
    }
}

// =================================================================================
// Single-fp16 GEMM via mma.sync.m16n8k16 (R11 champion, unchanged).
// MODE 0: Z  = kf_t(8192, K=256) . W0a  -> g_z  fp32
// MODE 1: yb = uf_t(32768, K=128) . W0b -> g_yb fp32
// MODE 2: out = W1(K=256) . h(32768)    -> dout (B,CO,N) fp32, bias+relu
// =================================================================================
static constexpr int STAGE_BYTES = 16384;
static constexpr int GEMM_SMEM   = 4 * STAGE_BYTES;   // 64 KB

template<int K>
__device__ __forceinline__ void load_stage(
        uint32_t sb, int stage,
        const __half* __restrict__ A, const __half* __restrict__ Bm,
        int m0, int n0, int k0, int tid) {
    uint32_t base = sb + (uint32_t)stage * STAGE_BYTES;
#pragma unroll
    for (int i = 0; i < 4; i++) {
        int e = tid + i * 256;
        int t = e >> 9;
        int l = e & 511;
        int r = l >> 2, q = l & 3;
        uint32_t dsw = SW128((uint32_t)(r * 64 + q * 16));
        const __half* src = (t == 0) ? (A  + (size_t)(m0 + r) * K + k0 + q * 8)
                                     : (Bm + (size_t)(n0 + r) * K + k0 + q * 8);
        cpa16(base + (uint32_t)t * 8192 + dsw, src);
    }
}

template<int MODE>
__global__ void __launch_bounds__(256, 2)
mma_gemm_kernel(float* __restrict__ dout) {
    constexpr int  K  = (MODE == 1) ? C1_ : 256;
    constexpr int  CH = K / 32;
    const __half* __restrict__ A  = (MODE == 0) ? g_kfh : (MODE == 1) ? g_ufh : g_W1h;
    const __half* __restrict__ Bm = (MODE == 0) ? g_W0a : (MODE == 1) ? g_W0b : g_hh;

    int m0 = (MODE == 2 ? blockIdx.x : blockIdx.y) * 128;
    int n0 = (MODE == 2 ? blockIdx.y : blockIdx.x) * 128;

    extern __shared__ char smem[];
    uint32_t sb = smem_u32(smem);
    int tid = threadIdx.x, wid = tid >> 5, lane = tid & 31;
    int warp_m = (wid & 1) * 64;
    int warp_n = (wid >> 1) * 32;

    float acc[4][4][4] = {};

    load_stage<K>(sb, 0, A, Bm, m0, n0, 0,  tid); CP_COMMIT();
    load_stage<K>(sb, 1, A, Bm, m0, n0, 32, tid); CP_COMMIT();
    load_stage<K>(sb, 2, A, Bm, m0, n0, 64, tid); CP_COMMIT();

    int lrow = lane & 15;
    int lcol = (lane >> 4) * 16;

    for (int c = 0; c < CH; c++) {
        CP_WAIT2();
        __syncthreads();
        if (c + 3 < CH)
            load_stage<K>(sb, (c + 3) & 3, A, Bm, m0, n0, (c + 3) * 32, tid);
        CP_COMMIT();

        uint32_t stg = sb + (uint32_t)(c & 3) * STAGE_BYTES;
#pragma unroll
        for (int kk = 0; kk < 2; kk++) {
            uint32_t a[4][4], b[4][2];
#pragma unroll
            for (int mt = 0; mt < 4; mt++) {
                uint32_t off = (uint32_t)((warp_m + mt * 16 + lrow) * 64 + kk * 32 + lcol);
                ldsm4(a[mt], stg + SW128(off));
            }
#pragma unroll
            for (int np = 0; np < 2; np++) {
                uint32_t off = (uint32_t)((warp_n + np * 16 + lrow) * 64 + kk * 32 + lcol);
                uint32_t r[4];
                ldsm4(r, stg + 8192 + SW128(off));
                b[np * 2][0] = r[0];     b[np * 2][1] = r[2];
                b[np * 2 + 1][0] = r[1]; b[np * 2 + 1][1] = r[3];
            }
#pragma unroll
            for (int mt = 0; mt < 4; mt++)
#pragma unroll
                for (int nt = 0; nt < 4; nt++)
                    mma16816(acc[mt][nt], a[mt], b[nt]);
        }
    }
    CP_WAITALL();

    int gr = lane >> 2;
    int gc = (lane & 3) * 2;

    if (MODE != 2) {
        float* out = (MODE == 0) ? g_z : g_yb;
#pragma unroll
        for (int mt = 0; mt < 4; mt++) {
#pragma unroll
            for (int half = 0; half < 2; half++) {
                int p = m0 + warp_m + mt * 16 + gr + half * 8;
#pragma unroll
                for (int nt = 0; nt < 4; nt++) {
                    int co = n0 + warp_n + nt * 8 + gc;
                    float2 v;
                    v.x = acc[mt][nt][half * 2 + 0];
                    v.y = acc[mt][nt][half * 2 + 1];
                    *(float2*)(out + (size_t)p * CO_ + co) = v;
                }
            }
        }
    } else {
#pragma unroll
        for (int mt = 0; mt < 4; mt++) {
            int co = m0 + warp_m + mt * 16 + gr;
            float bm0 = g_b1f[co], bm8 = g_b1f[co + 8];
#pragma unroll
            for (int nt = 0; nt < 4; nt++) {
                int pt = n0 + warp_n + nt * 8 + gc;
                int bb = pt >> 13;
                int nl = pt & (N_ - 1);
                float2 u0;
                u0.x = fmaxf(acc[mt][nt][0] + bm0, 0.f);
                u0.y = fmaxf(acc[mt][nt][1] + bm0, 0.f);
                *(float2*)(dout + ((size_t)(bb * CO_ + co)) * N_ + nl) = u0;
                float2 u1;
                u1.x = fmaxf(acc[mt][nt][2] + bm8, 0.f);
                u1.y = fmaxf(acc[mt][nt][3] + bm8, 0.f);
                *(float2*)(dout + ((size_t)(bb * CO_ + co + 8)) * N_ + nl) = u1;
            }
        }
    }
}

// ---------------- combine: h = relu(yb + sum wk * Z[idxk] + b0) fp16 -------------
__global__ void combine_kernel() {
    int lane = threadIdx.x & 31;
    int warp = threadIdx.x >> 5;
    int pid  = blockIdx.x * 8 + warp;
    int b    = pid >> 13;
    size_t base = (size_t)pid * 3;
    int i0 = g_idx[base + 0], i1 = g_idx[base + 1], i2 = g_idx[base + 2];
    float w0 = g_wgt[base + 0], w1 = g_wgt[base + 1], w2 = g_wgt[base + 2];
    const float4* yb = (const float4*)(g_yb + (size_t)pid * CO_);
    const float4* z0 = (const float4*)(g_z + ((size_t)(b * M_ + i0)) * CO_);
    const float4* z1 = (const float4*)(g_z + ((size_t)(b * M_ + i1)) * CO_);
    const float4* z2 = (const float4*)(g_z + ((size_t)(b * M_ + i2)) * CO_);
    const float4* bs = (const float4*)g_b0f;
    __half* hh = g_hh + (size_t)pid * K1_;
#pragma unroll
    for (int it = 0; it < 2; it++) {
        int c = lane + it * 32;
        float4 y = yb[c], a = z0[c], d = z1[c], e = z2[c], bb = bs[c];
        float v[4];
        v[0] = fmaxf(y.x + w0 * a.x + w1 * d.x + w2 * e.x + bb.x, 0.f);
        v[1] = fmaxf(y.y + w0 * a.y + w1 * d.y + w2 * e.y + bb.y, 0.f);
        v[2] = fmaxf(y.z + w0 * a.z + w1 * d.z + w2 * e.z + bb.z, 0.f);
        v[3] = fmaxf(y.w + w0 * a.w + w1 * d.w + w2 * e.w + bb.w, 0.f);
        __half2 h01 = __half2(__float2half_rn(v[0]), __float2half_rn(v[1]));
        __half2 h23 = __half2(__float2half_rn(v[2]), __float2half_rn(v[3]));
        *(__half2*)(hh + c * 4)     = h01;
        *(__half2*)(hh + c * 4 + 2) = h23;
    }
}

// ---------------- launch (single stream, strictly sequential) ---------------------
extern "C" void kernel_launch(void* const* d_in, const int* in_sizes, int n_in,
                              void* d_out, int out_size) {
    (void)in_sizes; (void)n_in; (void)out_size;
    const float* unknown = (const float*)d_in[0];
    const float* known   = (const float*)d_in[1];
    const float* uf      = (const float*)d_in[2];
    const float* kf      = (const float*)d_in[3];
    const float* W0  = (const float*)d_in[4];
    const float* b0  = (const float*)d_in[5];
    const float* g0  = (const float*)d_in[6];
    const float* be0 = (const float*)d_in[7];
    const float* rm0 = (const float*)d_in[8];
    const float* rv0 = (const float*)d_in[9];
    const float* W1  = (const float*)d_in[10];
    const float* b1  = (const float*)d_in[11];
    const float* g1  = (const float*)d_in[12];
    const float* be1 = (const float*)d_in[13];
    const float* rm1 = (const float*)d_in[14];
    const float* rv1 = (const float*)d_in[15];
    float* out = (float*)d_out;

    cudaFuncSetAttribute(mma_gemm_kernel<0>, cudaFuncAttributeMaxDynamicSharedMemorySize, GEMM_SMEM);
    cudaFuncSetAttribute(mma_gemm_kernel<1>, cudaFuncAttributeMaxDynamicSharedMemorySize, GEMM_SMEM);
    cudaFuncSetAttribute(mma_gemm_kernel<2>, cudaFuncAttributeMaxDynamicSharedMemorySize, GEMM_SMEM);

    fold_bn_kernel<<<640, 256>>>(W0, b0, g0, be0, rm0, rv0,
                                 W1, b1, g1, be1, rm1, rv1);

    transpose_all_kernel<<<2048 + 4096, dim3(32, 8)>>>(kf, uf);

    three_nn_kernel<<<dim3(N_ / 32, B_), 256>>>(unknown, known);

    mma_gemm_kernel<0><<<dim3(2, BM_ / 128), 256, GEMM_SMEM>>>(out);   // Z
    mma_gemm_kernel<1><<<dim3(2, BN_ / 128), 256, GEMM_SMEM>>>(out);   // YB
    combine_kernel<<<BN_ / 8, 256>>>();                                // h fp16
    mma_gemm_kernel<2><<<dim3(2, BN_ / 128), 256, GEMM_SMEM>>>(out);   // layer1
}

// round 14
// speedup vs baseline: 1.3290x; 1.1412x over previous
#include <cuda_runtime.h>
#include <cuda_fp16.h>
#include <math_constants.h>
#include <cstdint>

// Problem constants
#define B_  4
#define N_  8192
#define M_  2048
#define C1_ 128
#define C2_ 256
#define K0_ 384   // C1 + C2
#define K1_ 256
#define CO_ 256
#define BN_ (B_ * N_)
#define BM_ (B_ * M_)

// ---------------- scratch (static __device__ globals; no allocations) ----------
__device__ int   g_idx[(size_t)BN_ * 3];
__device__ float g_wgt[(size_t)BN_ * 3];
__device__ __align__(16) __half g_kfh[(size_t)BM_ * C2_];  // kf^T fp16 (B*M, 256)
__device__ __align__(16) __half g_ufh[(size_t)BN_ * C1_];  // uf^T fp16 (B*N, 128)
__device__ __align__(16) float  g_z [(size_t)BM_ * CO_];   // Z = kf^T . W0a^T fp32
__device__ __align__(16) float  g_yb[(size_t)BN_ * CO_];   // uf^T . W0b^T fp32
__device__ __align__(16) __half g_hh[(size_t)BN_ * K1_];   // layer0 out fp16 (B*N, 256)
__device__ __align__(16) __half g_W0a[CO_ * C2_];          // W0[:, 0:256]  fp16 (folded)
__device__ __align__(16) __half g_W0b[CO_ * C1_];          // W0[:, 256:384] fp16 (folded)
__device__ __align__(16) __half g_W1h[CO_ * K1_];
__device__ float g_b0f[CO_], g_b1f[CO_];

// ================= PTX helpers (baseline ISA only) ==============================
__device__ __forceinline__ uint32_t smem_u32(const void* p) {
    uint32_t a;
    asm("{ .reg .u64 t; cvta.to.shared.u64 t, %1; cvt.u32.u64 %0, t; }" : "=r"(a) : "l"(p));
    return a;
}
__device__ __forceinline__ void cpa16(uint32_t dst, const void* src) {
    asm volatile("cp.async.ca.shared.global [%0], [%1], 16;" :: "r"(dst), "l"(src));
}
#define CP_COMMIT()  asm volatile("cp.async.commit_group;" ::: "memory")
#define CP_WAIT2()   asm volatile("cp.async.wait_group 2;" ::: "memory")
#define CP_WAITALL() asm volatile("cp.async.wait_all;" ::: "memory")

__device__ __forceinline__ void ldsm4(uint32_t* r, uint32_t addr) {
    asm volatile("ldmatrix.sync.aligned.m8n8.x4.shared.b16 {%0,%1,%2,%3}, [%4];"
                 : "=r"(r[0]), "=r"(r[1]), "=r"(r[2]), "=r"(r[3]) : "r"(addr));
}
__device__ __forceinline__ void mma16816(float* c, const uint32_t* a, const uint32_t* b) {
    asm volatile("mma.sync.aligned.m16n8k16.row.col.f32.f16.f16.f32 "
                 "{%0,%1,%2,%3},{%4,%5,%6,%7},{%8,%9},{%0,%1,%2,%3};"
                 : "+f"(c[0]), "+f"(c[1]), "+f"(c[2]), "+f"(c[3])
                 : "r"(a[0]), "r"(a[1]), "r"(a[2]), "r"(a[3]), "r"(b[0]), "r"(b[1]));
}
#define SW128(o) ((o) ^ (((o) >> 3) & 0x70))

// ---------------- three_nn comparators (validated R10/R11) -----------------------
#define TNN_UPDATE(dv, mi)                                            \
    do {                                                              \
        if ((dv) < d2) {                                              \
            if ((dv) < d1) {                                          \
                d2 = d1; i2 = i1;                                     \
                if ((dv) < d0) { d1 = d0; i1 = i0; d0 = (dv); i0 = (mi); } \
                else           { d1 = (dv); i1 = (mi); }              \
            } else { d2 = (dv); i2 = (mi); }                          \
        }                                                             \
    } while (0)

#define TNN_LESS(dv, mi, d, i) ((dv) < (d) || ((dv) == (d) && (mi) < (i)))
#define TNN_UPDATE_TB(dv, mi)                                         \
    do {                                                              \
        if (TNN_LESS(dv, mi, d2, i2)) {                               \
            if (TNN_LESS(dv, mi, d1, i1)) {                           \
                d2 = d1; i2 = i1;                                     \
                if (TNN_LESS(dv, mi, d0, i0)) { d1 = d0; i1 = i0; d0 = (dv); i0 = (mi); } \
                else                          { d1 = (dv); i1 = (mi); } \
            } else { d2 = (dv); i2 = (mi); }                          \
        }                                                             \
    } while (0)

// =================================================================================
// PREP mega-kernel: all mutually-independent prep work in one launch.
//   blk [0, 1024)        : three_nn      (nb = blk & 255, b = blk >> 8)
//   blk [1024, 3072)     : kf transpose  (same mapping as R13 transpose_all)
//   blk [3072, 7168)     : uf transpose
//   blk [7168, 7552)     : fold0         (i stream identical to standalone)
//   blk [7552, 7808)     : fold1
// block = 256 threads (1-D). Shared: sk 32KB (+6KB merge tables); transpose tile
// aliases sk. All branches ~32 regs -> smem-limited occ 6 CTAs/SM.
// =================================================================================
__global__ void prep_kernel(const float* __restrict__ unknown, const float* __restrict__ known,
                            const float* __restrict__ kf, const float* __restrict__ uf,
                            const float* __restrict__ W0, const float* __restrict__ b0,
                            const float* __restrict__ g0, const float* __restrict__ be0,
                            const float* __restrict__ rm0, const float* __restrict__ rv0,
                            const float* __restrict__ W1, const float* __restrict__ b1,
                            const float* __restrict__ g1, const float* __restrict__ be1,
                            const float* __restrict__ rm1, const float* __restrict__ rv1) {
    __shared__ float4 sk[M_];          // 32 KB (three_nn points / transpose tile alias)
    __shared__ float  sd[8][3][32];
    __shared__ int    si[8][3][32];
    int blk = blockIdx.x;
    int t   = threadIdx.x;

    if (blk < 1024) {
        // ---------------- three_nn (R11 champion body) ----------------
        int nb = blk & 255;
        int b  = blk >> 8;
        const float* kb = known + (size_t)b * M_ * 3;
        for (int m = t; m < M_; m += 256) {
            float x = kb[m * 3 + 0], y = kb[m * 3 + 1], z = kb[m * 3 + 2];
            sk[m] = make_float4(x, y, z, x * x + y * y + z * z);
        }
        __syncthreads();

        int lane = t & 31;
        int w    = t >> 5;
        int n    = nb * 32 + lane;
        const float* u = unknown + ((size_t)b * N_ + n) * 3;
        float ux = u[0], uy = u[1], uz = u[2];
        float un = ux * ux + uy * uy + uz * uz;
        float ax = -2.f * ux, ay = -2.f * uy, az = -2.f * uz;

        float d0 = CUDART_INF_F, d1 = CUDART_INF_F, d2 = CUDART_INF_F;
        int   i0 = 0, i1 = 0, i2 = 0;
        int mStart = w * (M_ / 8);
        for (int m = mStart; m < mStart + M_ / 8; m += 4) {
            float4 pa = sk[m + 0];
            float4 pb = sk[m + 1];
            float4 pc = sk[m + 2];
            float4 pd = sk[m + 3];
            float da = fmaf(ax, pa.x, fmaf(ay, pa.y, fmaf(az, pa.z, un + pa.w)));
            float db = fmaf(ax, pb.x, fmaf(ay, pb.y, fmaf(az, pb.z, un + pb.w)));
            float dc = fmaf(ax, pc.x, fmaf(ay, pc.y, fmaf(az, pc.z, un + pc.w)));
            float dd = fmaf(ax, pd.x, fmaf(ay, pd.y, fmaf(az, pd.z, un + pd.w)));
            TNN_UPDATE(da, m + 0);
            TNN_UPDATE(db, m + 1);
            TNN_UPDATE(dc, m + 2);
            TNN_UPDATE(dd, m + 3);
        }
        sd[w][0][lane] = d0; si[w][0][lane] = i0;
        sd[w][1][lane] = d1; si[w][1][lane] = i1;
        sd[w][2][lane] = d2; si[w][2][lane] = i2;
        __syncthreads();

        if (w == 0) {
            d0 = d1 = d2 = CUDART_INF_F;
            i0 = i1 = i2 = 0;
#pragma unroll
            for (int ww = 0; ww < 8; ww++) {
#pragma unroll
                for (int k = 0; k < 3; k++) {
                    float dv = sd[ww][k][lane];
                    int   mi = si[ww][k][lane];
                    TNN_UPDATE_TB(dv, mi);
                }
            }
            float s0 = sqrtf(fmaxf(d0, 0.f)), s1 = sqrtf(fmaxf(d1, 0.f)), s2 = sqrtf(fmaxf(d2, 0.f));
            float r0 = 1.f / (s0 + 1e-8f), r1 = 1.f / (s1 + 1e-8f), r2 = 1.f / (s2 + 1e-8f);
            float rs = r0 + r1 + r2;
            size_t base = ((size_t)b * N_ + n) * 3;
            g_idx[base + 0] = i0; g_idx[base + 1] = i1; g_idx[base + 2] = i2;
            g_wgt[base + 0] = r0 / rs; g_wgt[base + 1] = r1 / rs; g_wgt[base + 2] = r2 / rs;
        }
    } else if (blk < 7168) {
        // ---------------- transposes (tile aliases sk) ----------------
        float (*tile)[33] = reinterpret_cast<float(*)[33]>(sk);
        int tx = t & 31, ty = t >> 5;
        int e = blk - 1024;
        if (e < 2048) {
            // kf: x = m-tile (64), y = c-tile (8), z = b (4)
            int bx = e & 63, rem = e >> 6;
            int by = rem & 7, b = rem >> 3;
            int m0 = bx * 32, c0 = by * 32;
#pragma unroll
            for (int j = 0; j < 32; j += 8)
                tile[ty + j][tx] = kf[((size_t)b * C2_ + c0 + ty + j) * M_ + m0 + tx];
            __syncthreads();
#pragma unroll
            for (int j = 0; j < 32; j += 8) {
                float v = tile[tx][ty + j];
                size_t o = ((size_t)b * M_ + m0 + ty + j) * C2_ + c0 + tx;
                g_kfh[o] = __float2half_rn(v);
            }
        } else {
            // uf: x = n-tile (256), y = c-tile (4), z = b (4)
            int e2 = e - 2048;
            int bx = e2 & 255, rem = e2 >> 8;
            int by = rem & 3, b = rem >> 2;
            int n0 = bx * 32, c0 = by * 32;
#pragma unroll
            for (int j = 0; j < 32; j += 8)
                tile[ty + j][tx] = uf[((size_t)b * C1_ + c0 + ty + j) * N_ + n0 + tx];
            __syncthreads();
#pragma unroll
            for (int j = 0; j < 32; j += 8) {
                float v = tile[tx][ty + j];
                size_t o = ((size_t)b * N_ + n0 + ty + j) * C1_ + c0 + tx;
                g_ufh[o] = __float2half_rn(v);
            }
        }
    } else if (blk < 7552) {
        // ---------------- fold0 ----------------
        int i = (blk - 7168) * 256 + t;
        if (i < CO_ * K0_) {
            int co = i / K0_, col = i - co * K0_;
            float s = g0[co] / sqrtf(rv0[co] + 1e-5f);
            __half w = __float2half_rn(W0[i] * s);
            if (col < C2_) g_W0a[co * C2_ + col] = w;
            else           g_W0b[co * C1_ + (col - C2_)] = w;
        }
        if (i < CO_) {
            float s = g0[i] / sqrtf(rv0[i] + 1e-5f);
            g_b0f[i] = (b0[i] - rm0[i]) * s + be0[i];
        }
    } else {
        // ---------------- fold1 ----------------
        int i = (blk - 7552) * 256 + t;
        if (i < CO_ * K1_) {
            int co = i / K1_;
            float s = g1[co] / sqrtf(rv1[co] + 1e-5f);
            g_W1h[i] = __float2half_rn(W1[i] * s);
        }
        if (i < CO_) {
            float s = g1[i] / sqrtf(rv1[i] + 1e-5f);
            g_b1f[i] = (b1[i] - rm1[i]) * s + be1[i];
        }
    }
}

// =================================================================================
// Single-fp16 GEMM body via mma.sync.m16n8k16 (unchanged math).
// MODE 0: Z  = kf_t(8192, K=256) . W0a  -> g_z  fp32
// MODE 1: yb = uf_t(32768, K=128) . W0b -> g_yb fp32
// MODE 2: out = W1(K=256) . h(32768)    -> dout (B,CO,N) fp32, bias+relu
// =================================================================================
static constexpr int STAGE_BYTES = 16384;
static constexpr int GEMM_SMEM   = 4 * STAGE_BYTES;   // 64 KB

template<int K>
__device__ __forceinline__ void load_stage(
        uint32_t sb, int stage,
        const __half* __restrict__ A, const __half* __restrict__ Bm,
        int m0, int n0, int k0, int tid) {
    uint32_t base = sb + (uint32_t)stage * STAGE_BYTES;
#pragma unroll
    for (int i = 0; i < 4; i++) {
        int e = tid + i * 256;
        int t = e >> 9;
        int l = e & 511;
        int r = l >> 2, q = l & 3;
        uint32_t dsw = SW128((uint32_t)(r * 64 + q * 16));
        const __half* src = (t == 0) ? (A  + (size_t)(m0 + r) * K + k0 + q * 8)
                                     : (Bm + (size_t)(n0 + r) * K + k0 + q * 8);
        cpa16(base + (uint32_t)t * 8192 + dsw, src);
    }
}

template<int MODE>
__device__ void gemm_body(float* __restrict__ dout, int bx, int by) {
    constexpr int  K  = (MODE == 1) ? C1_ : 256;
    constexpr int  CH = K / 32;
    const __half* __restrict__ A  = (MODE == 0) ? g_kfh : (MODE == 1) ? g_ufh : g_W1h;
    const __half* __restrict__ Bm = (MODE == 0) ? g_W0a : (MODE == 1) ? g_W0b : g_hh;

    int m0 = (MODE == 2 ? bx : by) * 128;
    int n0 = (MODE == 2 ? by : bx) * 128;

    extern __shared__ char smem[];
    uint32_t sb = smem_u32(smem);
    int tid = threadIdx.x, wid = tid >> 5, lane = tid & 31;
    int warp_m = (wid & 1) * 64;
    int warp_n = (wid >> 1) * 32;

    float acc[4][4][4] = {};

    load_stage<K>(sb, 0, A, Bm, m0, n0, 0,  tid); CP_COMMIT();
    load_stage<K>(sb, 1, A, Bm, m0, n0, 32, tid); CP_COMMIT();
    load_stage<K>(sb, 2, A, Bm, m0, n0, 64, tid); CP_COMMIT();

    int lrow = lane & 15;
    int lcol = (lane >> 4) * 16;

    for (int c = 0; c < CH; c++) {
        CP_WAIT2();
        __syncthreads();
        if (c + 3 < CH)
            load_stage<K>(sb, (c + 3) & 3, A, Bm, m0, n0, (c + 3) * 32, tid);
        CP_COMMIT();

        uint32_t stg = sb + (uint32_t)(c & 3) * STAGE_BYTES;
#pragma unroll
        for (int kk = 0; kk < 2; kk++) {
            uint32_t a[4][4], b[4][2];
#pragma unroll
            for (int mt = 0; mt < 4; mt++) {
                uint32_t off = (uint32_t)((warp_m + mt * 16 + lrow) * 64 + kk * 32 + lcol);
                ldsm4(a[mt], stg + SW128(off));
            }
#pragma unroll
            for (int np = 0; np < 2; np++) {
                uint32_t off = (uint32_t)((warp_n + np * 16 + lrow) * 64 + kk * 32 + lcol);
                uint32_t r[4];
                ldsm4(r, stg + 8192 + SW128(off));
                b[np * 2][0] = r[0];     b[np * 2][1] = r[2];
                b[np * 2 + 1][0] = r[1]; b[np * 2 + 1][1] = r[3];
            }
#pragma unroll
            for (int mt = 0; mt < 4; mt++)
#pragma unroll
                for (int nt = 0; nt < 4; nt++)
                    mma16816(acc[mt][nt], a[mt], b[nt]);
        }
    }
    CP_WAITALL();

    int gr = lane >> 2;
    int gc = (lane & 3) * 2;

    if (MODE != 2) {
        float* out = (MODE == 0) ? g_z : g_yb;
#pragma unroll
        for (int mt = 0; mt < 4; mt++) {
#pragma unroll
            for (int half = 0; half < 2; half++) {
                int p = m0 + warp_m + mt * 16 + gr + half * 8;
#pragma unroll
                for (int nt = 0; nt < 4; nt++) {
                    int co = n0 + warp_n + nt * 8 + gc;
                    float2 v;
                    v.x = acc[mt][nt][half * 2 + 0];
                    v.y = acc[mt][nt][half * 2 + 1];
                    *(float2*)(out + (size_t)p * CO_ + co) = v;
                }
            }
        }
    } else {
#pragma unroll
        for (int mt = 0; mt < 4; mt++) {
            int co = m0 + warp_m + mt * 16 + gr;
            float bm0 = g_b1f[co], bm8 = g_b1f[co + 8];
#pragma unroll
            for (int nt = 0; nt < 4; nt++) {
                int pt = n0 + warp_n + nt * 8 + gc;
                int bb = pt >> 13;
                int nl = pt & (N_ - 1);
                float2 u0;
                u0.x = fmaxf(acc[mt][nt][0] + bm0, 0.f);
                u0.y = fmaxf(acc[mt][nt][1] + bm0, 0.f);
                *(float2*)(dout + ((size_t)(bb * CO_ + co)) * N_ + nl) = u0;
                float2 u1;
                u1.x = fmaxf(acc[mt][nt][2] + bm8, 0.f);
                u1.y = fmaxf(acc[mt][nt][3] + bm8, 0.f);
                *(float2*)(dout + ((size_t)(bb * CO_ + co + 8)) * N_ + nl) = u1;
            }
        }
    }
}

// ---------------- merged GEMM0+GEMM1 (homogeneous fusion) ------------------------
// grid (2, 320): y < 64 -> Z GEMM (by = y), else YB GEMM (by = y - 64)
__global__ void __launch_bounds__(256, 2)
gemm01_kernel(float* __restrict__ dout) {
    if (blockIdx.y < (BM_ / 128)) gemm_body<0>(dout, blockIdx.x, blockIdx.y);
    else                          gemm_body<1>(dout, blockIdx.x, blockIdx.y - (BM_ / 128));
}

// ---------------- layer-1 GEMM ----------------------------------------------------
__global__ void __launch_bounds__(256, 2)
gemm2_kernel(float* __restrict__ dout) {
    gemm_body<2>(dout, blockIdx.x, blockIdx.y);
}

// ---------------- combine: h = relu(yb + sum wk * Z[idxk] + b0) fp16 -------------
__global__ void combine_kernel() {
    int lane = threadIdx.x & 31;
    int warp = threadIdx.x >> 5;
    int pid  = blockIdx.x * 8 + warp;
    int b    = pid >> 13;
    size_t base = (size_t)pid * 3;
    int i0 = g_idx[base + 0], i1 = g_idx[base + 1], i2 = g_idx[base + 2];
    float w0 = g_wgt[base + 0], w1 = g_wgt[base + 1], w2 = g_wgt[base + 2];
    const float4* yb = (const float4*)(g_yb + (size_t)pid * CO_);
    const float4* z0 = (const float4*)(g_z + ((size_t)(b * M_ + i0)) * CO_);
    const float4* z1 = (const float4*)(g_z + ((size_t)(b * M_ + i1)) * CO_);
    const float4* z2 = (const float4*)(g_z + ((size_t)(b * M_ + i2)) * CO_);
    const float4* bs = (const float4*)g_b0f;
    __half* hh = g_hh + (size_t)pid * K1_;
#pragma unroll
    for (int it = 0; it < 2; it++) {
        int c = lane + it * 32;
        float4 y = yb[c], a = z0[c], d = z1[c], e = z2[c], bb = bs[c];
        float v[4];
        v[0] = fmaxf(y.x + w0 * a.x + w1 * d.x + w2 * e.x + bb.x, 0.f);
        v[1] = fmaxf(y.y + w0 * a.y + w1 * d.y + w2 * e.y + bb.y, 0.f);
        v[2] = fmaxf(y.z + w0 * a.z + w1 * d.z + w2 * e.z + bb.z, 0.f);
        v[3] = fmaxf(y.w + w0 * a.w + w1 * d.w + w2 * e.w + bb.w, 0.f);
        __half2 h01 = __half2(__float2half_rn(v[0]), __float2half_rn(v[1]));
        __half2 h23 = __half2(__float2half_rn(v[2]), __float2half_rn(v[3]));
        *(__half2*)(hh + c * 4)     = h01;
        *(__half2*)(hh + c * 4 + 2) = h23;
    }
}

// ---------------- launch (single stream, strictly sequential) ---------------------
extern "C" void kernel_launch(void* const* d_in, const int* in_sizes, int n_in,
                              void* d_out, int out_size) {
    (void)in_sizes; (void)n_in; (void)out_size;
    const float* unknown = (const float*)d_in[0];
    const float* known   = (const float*)d_in[1];
    const float* uf      = (const float*)d_in[2];
    const float* kf      = (const float*)d_in[3];
    const float* W0  = (const float*)d_in[4];
    const float* b0  = (const float*)d_in[5];
    const float* g0  = (const float*)d_in[6];
    const float* be0 = (const float*)d_in[7];
    const float* rm0 = (const float*)d_in[8];
    const float* rv0 = (const float*)d_in[9];
    const float* W1  = (const float*)d_in[10];
    const float* b1  = (const float*)d_in[11];
    const float* g1  = (const float*)d_in[12];
    const float* be1 = (const float*)d_in[13];
    const float* rm1 = (const float*)d_in[14];
    const float* rv1 = (const float*)d_in[15];
    float* out = (float*)d_out;

    cudaFuncSetAttribute(gemm01_kernel, cudaFuncAttributeMaxDynamicSharedMemorySize, GEMM_SMEM);
    cudaFuncSetAttribute(gemm2_kernel,  cudaFuncAttributeMaxDynamicSharedMemorySize, GEMM_SMEM);

    // 1) all independent prep: three_nn + transposes + folds
    prep_kernel<<<7808, 256>>>(unknown, known, kf, uf,
                               W0, b0, g0, be0, rm0, rv0,
                               W1, b1, g1, be1, rm1, rv1);

    // 2) Z GEMM + YB GEMM merged (homogeneous)
    gemm01_kernel<<<dim3(2, (BM_ / 128) + (BN_ / 128)), 256, GEMM_SMEM>>>(out);

    // 3) combine -> h fp16
    combine_kernel<<<BN_ / 8, 256>>>();

    // 4) layer-1 GEMM -> output
    gemm2_kernel<<<dim3(2, BN_ / 128), 256, GEMM_SMEM>>>(out);
}